// round 10
// baseline (speedup 1.0000x reference)
#include <cuda_runtime.h>
#include <cuda_bf16.h>
#include <cstdint>

#define BATCH 2048
#define CAND  16
#define DIM   256
#define ADJW  96                    // 2*3*16
#define OUTW  (DIM + ADJW + 1)      // 353
#define THRED 0.8f
#define CHUNK 32                    // batches per k_neigh block

// ---- fused sim kernel geometry ----
#define NB     2                    // batches per block
#define SLOTS  (NB + 6)             // 8 batch tiles incl. +-3 halo
#define BPAD   264                  // bf16 row stride (132 words == 4 mod 32: ldsm clean)
#define FTHR   384                  // threads (12 warps = 12 (bi,cp) tasks)
#define NROWST (SLOTS * CAND)       // 128 tile rows

#define OFF_TILES  0
#define SZ_TILES   (NROWST * BPAD * 2)                  // 67584 B
#define OFF_RSUM   (OFF_TILES + SZ_TILES)
#define SZ_RSUM    (NB * 6 * CAND * 4)                  // 768 B
#define OFF_INVS   (OFF_RSUM + SZ_RSUM)
#define SZ_INVS    (NB * CAND * 4)                      // 128 B
#define OFF_INVN   (OFF_INVS + SZ_INVS)
#define SZ_INVN    (NROWST * 4)                         // 512 B
#define OFF_NSQ    (OFF_INVN + SZ_INVN)
#define SZ_NSQ     (NROWST * 4)                         // 512 B
#define OFF_NMV    (OFF_NSQ + SZ_NSQ)
#define SZ_NMV     (NROWST * 4)                         // 512 B
#define SMEM_TOTAL (OFF_NMV + SZ_NMV)                   // 70016 B -> 3 CTAs/SM

#define FGRID (BATCH / NB)                              // 1024 blocks

__device__ __forceinline__ uint32_t smem_u32(const void* p) {
    uint32_t a;
    asm("{ .reg .u64 t; cvta.to.shared.u64 t, %1; cvt.u32.u64 %0, t; }"
        : "=r"(a) : "l"(p));
    return a;
}

__device__ __forceinline__ void ldsm4(uint32_t addr, uint32_t& r0, uint32_t& r1,
                                      uint32_t& r2, uint32_t& r3) {
    asm volatile("ldmatrix.sync.aligned.m8n8.x4.shared.b16 {%0,%1,%2,%3}, [%4];"
                 : "=r"(r0), "=r"(r1), "=r"(r2), "=r"(r3) : "r"(addr));
}

__device__ __forceinline__ void mma16816(float* c, uint32_t a0, uint32_t a1,
                                         uint32_t a2, uint32_t a3,
                                         uint32_t b0, uint32_t b1) {
    asm volatile(
        "mma.sync.aligned.m16n8k16.row.col.f32.bf16.bf16.f32 "
        "{%0,%1,%2,%3}, {%4,%5,%6,%7}, {%8,%9}, {%0,%1,%2,%3};\n"
        : "+f"(c[0]), "+f"(c[1]), "+f"(c[2]), "+f"(c[3])
        : "r"(a0), "r"(a1), "r"(a2), "r"(a3), "r"(b0), "r"(b1));
}

// ---------------------------------------------------------------------------
// K_neigh: neighbor-mean (output cols [0,256)). Rolling 7-batch window.
// ---------------------------------------------------------------------------
__global__ __launch_bounds__(256) void k_neigh(const float* __restrict__ emb,
                                               const int* __restrict__ nm,
                                               float* __restrict__ out) {
    const int d4 = threadIdx.x;                       // 0..63
    const int c  = blockIdx.y * 4 + threadIdx.y;      // 0..15
    const int b0 = blockIdx.x * CHUNK;

    auto loadE = [&](int bb) -> float4 {
        if ((unsigned)bb < BATCH)
            return reinterpret_cast<const float4*>(emb)[((size_t)bb * CAND + c) * (DIM / 4) + d4];
        return make_float4(0.f, 0.f, 0.f, 0.f);
    };
    auto loadM = [&](int bb) -> float {
        if ((unsigned)bb < BATCH) return (float)nm[bb * CAND + c];
        return 0.f;
    };

    float4 w[7];
    float  m[6];
    #pragma unroll
    for (int i = 0; i < 7; i++) w[i] = loadE(b0 - 3 + i);
    #pragma unroll
    for (int i = 0; i < 6; i++) m[i] = loadM(b0 - 3 + i);

    #pragma unroll 8
    for (int s = 0; s < CHUNK; s++) {
        const int b = b0 + s;
        const float L1 = m[2], L2 = m[2] * m[1], L3 = m[2] * m[1] * m[0];
        const float R1 = m[3], R2 = m[3] * m[4], R3 = m[3] * m[4] * m[5];
        float4 acc;
        acc.x = (w[2].x*L1 + w[1].x*L2 + w[0].x*L3 + w[4].x*R1 + w[5].x*R2 + w[6].x*R3) * (1.f/6.f);
        acc.y = (w[2].y*L1 + w[1].y*L2 + w[0].y*L3 + w[4].y*R1 + w[5].y*R2 + w[6].y*R3) * (1.f/6.f);
        acc.z = (w[2].z*L1 + w[1].z*L2 + w[0].z*L3 + w[4].z*R1 + w[5].z*R2 + w[6].z*R3) * (1.f/6.f);
        acc.w = (w[2].w*L1 + w[1].w*L2 + w[0].w*L3 + w[4].w*R1 + w[5].w*R2 + w[6].w*R3) * (1.f/6.f);
        float* o = out + (size_t)(b * CAND + c) * OUTW + d4 * 4;
        o[0] = acc.x; o[1] = acc.y; o[2] = acc.z; o[3] = acc.w;
        #pragma unroll
        for (int i = 0; i < 6; i++) w[i] = w[i + 1];
        w[6] = loadE(b + 4);
        #pragma unroll
        for (int i = 0; i < 5; i++) m[i] = m[i + 1];
        m[5] = loadM(b + 3);
    }
}

// ---------------------------------------------------------------------------
// K_fused: band cosine adjacency (output cols [256,353)).
// One warp per (bi, cp) task: NB=2 -> 12 warps/block, 1024 blocks, 3 CTAs/SM.
// Raw bf16 tiles; norms accumulated in load phase; ldmatrix fragment loads.
// OOB batches are zero tiles + zero masks => boundary sims exactly 0.
// ---------------------------------------------------------------------------
__global__ __launch_bounds__(FTHR, 3) void k_fused(const float* __restrict__ emb,
                                                   const int* __restrict__ nm,
                                                   float* __restrict__ out) {
    extern __shared__ __align__(16) char smraw[];
    __nv_bfloat16* tiles = reinterpret_cast<__nv_bfloat16*>(smraw + OFF_TILES); // [128][264]
    float* rsum = reinterpret_cast<float*>(smraw + OFF_RSUM);                   // [NB][6][16]
    float* invs = reinterpret_cast<float*>(smraw + OFF_INVS);                   // [NB][16]
    float* invn = reinterpret_cast<float*>(smraw + OFF_INVN);                   // [128]
    float* nsq  = reinterpret_cast<float*>(smraw + OFF_NSQ);                    // [128]
    float* nmv  = reinterpret_cast<float*>(smraw + OFF_NMV);                    // [128]

    const int b0   = blockIdx.x * NB;
    const int t    = threadIdx.x;
    const int wid  = t >> 5;
    const int lane = t & 31;

    // ---- mask cache: nmv[slot][j] (OOB batches -> 0) ----
    if (t < NROWST) {
        const int bb = b0 - 3 + (t >> 4);
        nmv[t] = ((unsigned)bb < BATCH) ? (float)nm[bb * CAND + (t & 15)] : 0.f;
    }

    // ---- load + norm-accumulate: 128 rows round-robin over 12 warps ----
    const int l8 = lane * 8;
    for (int r = wid; r < NROWST; r += FTHR / 32) {
        const int bb = b0 - 3 + (r >> 4);
        float4 v0 = make_float4(0.f, 0.f, 0.f, 0.f);
        float4 v1 = v0;
        if ((unsigned)bb < BATCH) {
            const float4* src = reinterpret_cast<const float4*>(
                emb + ((size_t)bb * CAND + (r & 15)) * DIM);
            v0 = src[lane * 2];
            v1 = src[lane * 2 + 1];
        }
        __nv_bfloat162 o[4];
        o[0] = __floats2bfloat162_rn(v0.x, v0.y);
        o[1] = __floats2bfloat162_rn(v0.z, v0.w);
        o[2] = __floats2bfloat162_rn(v1.x, v1.y);
        o[3] = __floats2bfloat162_rn(v1.z, v1.w);
        *reinterpret_cast<uint4*>(&tiles[(size_t)r * BPAD + l8]) = *reinterpret_cast<uint4*>(o);
        float ss = v0.x*v0.x + v0.y*v0.y + v0.z*v0.z + v0.w*v0.w
                 + v1.x*v1.x + v1.y*v1.y + v1.z*v1.z + v1.w*v1.w;
        #pragma unroll
        for (int off = 16; off; off >>= 1) ss += __shfl_xor_sync(0xffffffffu, ss, off);
        if (lane == 0) nsq[r] = ss;
    }
    __syncthreads();

    if (t < NROWST) invn[t] = rsqrtf(fmaxf(nsq[t], 1e-12f));

    // ---- task mapping: warp wid -> bi = wid/6, cp = wid%6 ----
    const int g  = lane >> 2;           // 0..7
    const int tg = lane & 3;            // 0..3
    const int jb = tg * 2;
    const int bi = wid / 6;             // 0..1
    const int cp = wid % 6;             // 0..5
    const int slot = bi + 3;
    const int bslot = (cp < 3) ? (slot - 1 - cp) : (slot + cp - 2);

    const int lmoff = (lane & 15) * BPAD + (lane >> 4) * 8;   // elements
    const uint32_t tiles_base = smem_u32(tiles);
    uint32_t aad = tiles_base + (uint32_t)(slot * CAND * BPAD + lmoff) * 2;
    uint32_t bad = tiles_base + (uint32_t)(bslot * CAND * BPAD + lmoff) * 2;

    float acc[8];
    #pragma unroll
    for (int x = 0; x < 8; x++) acc[x] = 0.f;

    #pragma unroll
    for (int kt = 0; kt < DIM / 16; kt++) {
        uint32_t a0, a1, a2, a3;
        ldsm4(aad, a0, a1, a2, a3);
        aad += 32;
        uint32_t m0, m1, m2, m3;    // {B[g][k0], B[g+8][k0], B[g][k0+8], B[g+8][k0+8]}
        ldsm4(bad, m0, m1, m2, m3);
        bad += 32;
        mma16816(acc,     a0, a1, a2, a3, m0, m2);   // cols jb..: n = g
        mma16816(acc + 4, a0, a1, a2, a3, m1, m3);   // cols jb+8..: n = g+8
    }
    __syncthreads();   // invn visible block-wide (tiles reads done)

    // ---- gates from mask cache: cumulative product toward the side ----
    float gj[4];
    const int js[4] = {jb, jb + 1, jb + 8, jb + 9};
    #pragma unroll
    for (int jx = 0; jx < 4; jx++) {
        float gg = 1.f;
        if (cp < 3) {          // left k = cp+1: masks of batches b-1..b-k
            #pragma unroll
            for (int q = 1; q <= 3; q++)
                if (q <= cp + 1) gg *= nmv[(slot - q) * CAND + js[jx]];
        } else {               // right k = cp-2: masks of batches b..b+k-1
            #pragma unroll
            for (int q = 0; q < 3; q++)
                if (q < cp - 2) gg *= nmv[(slot + q) * CAND + js[jx]];
        }
        gj[jx] = gg;
    }

    // ---- epilogue: cosine scale, threshold, gate, partial row sums ----
    const float inA0 = invn[slot * CAND + g];
    const float inA8 = invn[slot * CAND + g + 8];
    const float* np = &invn[bslot * CAND];
    const float ib0 = np[jb], ib1 = np[jb + 1], ib8 = np[jb + 8], ib9 = np[jb + 9];
    auto thr = [](float v, float ge) {
        v = (v > THRED) ? fminf(v, 1.f) : 0.f;
        return v * ge;
    };
    acc[0] = thr(acc[0] * inA0 * ib0, gj[0]);
    acc[1] = thr(acc[1] * inA0 * ib1, gj[1]);
    acc[2] = thr(acc[2] * inA8 * ib0, gj[0]);
    acc[3] = thr(acc[3] * inA8 * ib1, gj[1]);
    acc[4] = thr(acc[4] * inA0 * ib8, gj[2]);
    acc[5] = thr(acc[5] * inA0 * ib9, gj[3]);
    acc[6] = thr(acc[6] * inA8 * ib8, gj[2]);
    acc[7] = thr(acc[7] * inA8 * ib9, gj[3]);

    float sA = acc[0] + acc[1] + acc[4] + acc[5];   // row g
    float sB = acc[2] + acc[3] + acc[6] + acc[7];   // row g+8
    sA += __shfl_xor_sync(0xffffffffu, sA, 1);
    sA += __shfl_xor_sync(0xffffffffu, sA, 2);
    sB += __shfl_xor_sync(0xffffffffu, sB, 1);
    sB += __shfl_xor_sync(0xffffffffu, sB, 2);
    if (tg == 0) {
        rsum[(bi * 6 + cp) * CAND + g]     = sA;
        rsum[(bi * 6 + cp) * CAND + g + 8] = sB;
    }
    __syncthreads();

    // ---- invs: per output row 1 / (L1 sum + ones col) ----
    if (t < NB * CAND) {
        const int tb = t >> 4, i = t & 15;
        float s = 1.0f;
        #pragma unroll
        for (int c2 = 0; c2 < 6; c2++) s += rsum[(tb * 6 + c2) * CAND + i];
        invs[t] = 1.0f / fmaxf(s, 1e-12f);
    }
    __syncthreads();

    // ---- normalized writes ----
    {
        const float ivA = invs[bi * CAND + g];
        const float ivB = invs[bi * CAND + g + 8];
        float* oA = out + (size_t)((b0 + bi) * CAND + g)     * OUTW + DIM + cp * CAND + jb;
        float* oB = out + (size_t)((b0 + bi) * CAND + g + 8) * OUTW + DIM + cp * CAND + jb;
        oA[0] = acc[0] * ivA;  oA[1] = acc[1] * ivA;
        oA[8] = acc[4] * ivA;  oA[9] = acc[5] * ivA;
        oB[0] = acc[2] * ivB;  oB[1] = acc[3] * ivB;
        oB[8] = acc[6] * ivB;  oB[9] = acc[7] * ivB;
    }
    if (t < NB * CAND) {
        out[(size_t)(b0 * CAND + t) * OUTW + DIM + ADJW] = invs[t];  // ones column * inv
    }
}

// ---------------------------------------------------------------------------
extern "C" void kernel_launch(void* const* d_in, const int* in_sizes, int n_in,
                              void* d_out, int out_size) {
    (void)in_sizes; (void)n_in; (void)out_size;
    const float* emb = (const float*)d_in[0];
    const int*   nm  = (const int*)d_in[1];
    float*       out = (float*)d_out;

    (void)cudaFuncSetAttribute(k_fused, cudaFuncAttributeMaxDynamicSharedMemorySize,
                               SMEM_TOTAL);

    dim3 nb(64, 4);
    dim3 ng(BATCH / CHUNK, 4);
    k_neigh<<<ng, nb>>>(emb, nm, out);

    k_fused<<<FGRID, FTHR, SMEM_TOTAL>>>(emb, nm, out);
}